// round 1
// baseline (speedup 1.0000x reference)
#include <cuda_runtime.h>

// Scratch accumulators (allocation-free: __device__ globals).
__device__ double g_num;
__device__ double g_den;

__global__ void eau_zero_kernel() {
    g_num = 0.0;
    g_den = 0.0;
}

// Returns r = 1/(exp(2x)+1).  Then:  1 - tanh(x) = 2r,  tanh(x) = 1 - 2r.
__device__ __forceinline__ float half_logistic(float x) {
    float e, r;
    // exp(2x) = 2^(2x * log2(e))
    asm("ex2.approx.f32 %0, %1;" : "=f"(e) : "f"(x * 2.8853900817779268f));
    asm("rcp.approx.f32 %0, %1;" : "=f"(r) : "f"(e + 1.0f));
    return r;
}

__global__ void __launch_bounds__(256) eau_reduce_kernel(
    const float* __restrict__ err,
    const float* __restrict__ unc,
    const float* __restrict__ eth_p,
    const float* __restrict__ uth_p,
    int n)
{
    const float eth = *eth_p;
    const float uth = *uth_p;

    float num = 0.0f;
    float den = 0.0f;

    const int tid    = blockIdx.x * blockDim.x + threadIdx.x;
    const int stride = gridDim.x * blockDim.x;

    const int n4 = n >> 2;  // number of float4 elements
    const float4* e4 = reinterpret_cast<const float4*>(err);
    const float4* u4 = reinterpret_cast<const float4*>(unc);

    for (int i = tid; i < n4; i += stride) {
        float4 ev = e4[i];
        float4 uv = u4[i];
        const float ea[4] = {ev.x, ev.y, ev.z, ev.w};
        const float ua[4] = {uv.x, uv.y, uv.z, uv.w};
        #pragma unroll
        for (int k = 0; k < 4; k++) {
            float e = ea[k];
            float u = ua[k];
            float re = half_logistic(e);   // 1 - tanh(e) = 2*re
            float ru = half_logistic(u);
            bool  lo = (e <= eth);
            bool  ce = (u <= uth);
            float fe = lo ? (2.0f * re) : (1.0f - 2.0f * re);  // lo ? (1-te) : te
            float fu = ce ? (2.0f * ru) : (1.0f - 2.0f * ru);  // ce ? (1-tu) : tu
            float p  = fe * fu;
            den += p;
            num += (lo == ce) ? p : 0.0f;
        }
    }

    // Scalar tail (N is 2^24 here, but stay general).
    for (int i = (n4 << 2) + tid; i < n; i += stride) {
        float e = err[i];
        float u = unc[i];
        float re = half_logistic(e);
        float ru = half_logistic(u);
        bool  lo = (e <= eth);
        bool  ce = (u <= uth);
        float fe = lo ? (2.0f * re) : (1.0f - 2.0f * re);
        float fu = ce ? (2.0f * ru) : (1.0f - 2.0f * ru);
        float p  = fe * fu;
        den += p;
        num += (lo == ce) ? p : 0.0f;
    }

    // Warp reduction.
    #pragma unroll
    for (int off = 16; off > 0; off >>= 1) {
        num += __shfl_xor_sync(0xffffffffu, num, off);
        den += __shfl_xor_sync(0xffffffffu, den, off);
    }

    // Block reduction via shared memory.
    __shared__ float s_num[8];
    __shared__ float s_den[8];
    const int lane = threadIdx.x & 31;
    const int wid  = threadIdx.x >> 5;
    if (lane == 0) {
        s_num[wid] = num;
        s_den[wid] = den;
    }
    __syncthreads();
    if (wid == 0) {
        const int nw = blockDim.x >> 5;
        num = (lane < nw) ? s_num[lane] : 0.0f;
        den = (lane < nw) ? s_den[lane] : 0.0f;
        #pragma unroll
        for (int off = 4; off > 0; off >>= 1) {
            num += __shfl_xor_sync(0xffffffffu, num, off);
            den += __shfl_xor_sync(0xffffffffu, den, off);
        }
        if (lane == 0) {
            atomicAdd(&g_num, (double)num);
            atomicAdd(&g_den, (double)den);
        }
    }
}

__global__ void eau_finalize_kernel(float* __restrict__ out) {
    double eau  = g_num / (g_den + 1e-10);
    double loss = -1.0 * log(eau + 1e-10);
    out[0] = (float)loss;
}

extern "C" void kernel_launch(void* const* d_in, const int* in_sizes, int n_in,
                              void* d_out, int out_size)
{
    const float* err   = (const float*)d_in[0];
    const float* unc   = (const float*)d_in[1];
    const float* eth_p = (const float*)d_in[2];
    const float* uth_p = (const float*)d_in[3];
    float* out = (float*)d_out;
    const int n = in_sizes[0];

    eau_zero_kernel<<<1, 1>>>();
    eau_reduce_kernel<<<2048, 256>>>(err, unc, eth_p, uth_p, n);
    eau_finalize_kernel<<<1, 1>>>(out);
}

// round 2
// speedup vs baseline: 1.0614x; 1.0614x over previous
#include <cuda_runtime.h>

// Scratch state (allocation-free: __device__ globals, zero-initialized at load).
// Invariant: outside of a kernel_launch execution these are all zero — the
// last block resets them after computing the result, so every graph replay
// sees identical initial state.
__device__ double   g_num;
__device__ double   g_den;
__device__ unsigned g_count;

// r = 1/(exp(2x)+1).  Then  1 - tanh(x) = 2r,  tanh(x) = 1 - 2r.
__device__ __forceinline__ float half_logistic(float x) {
    float e, r;
    asm("ex2.approx.f32 %0, %1;" : "=f"(e) : "f"(x * 2.8853900817779268f));
    asm("rcp.approx.f32 %0, %1;" : "=f"(r) : "f"(e + 1.0f));
    return r;
}

__global__ void __launch_bounds__(256) eau_fused_kernel(
    const float* __restrict__ err,
    const float* __restrict__ unc,
    const float* __restrict__ eth_p,
    const float* __restrict__ uth_p,
    float* __restrict__ out,
    int n)
{
    const float eth = *eth_p;
    const float uth = *uth_p;

    float num = 0.0f;
    float den = 0.0f;

    const int tid    = blockIdx.x * blockDim.x + threadIdx.x;
    const int stride = gridDim.x * blockDim.x;

    const int n4 = n >> 2;
    const float4* e4 = reinterpret_cast<const float4*>(err);
    const float4* u4 = reinterpret_cast<const float4*>(unc);

    for (int i = tid; i < n4; i += stride) {
        float4 ev = e4[i];
        float4 uv = u4[i];
        const float ea[4] = {ev.x, ev.y, ev.z, ev.w};
        const float ua[4] = {uv.x, uv.y, uv.z, uv.w};
        #pragma unroll
        for (int k = 0; k < 4; k++) {
            float e  = ea[k];
            float u  = ua[k];
            float re = half_logistic(e);   // (1 - tanh e) = 2*re
            float ru = half_logistic(u);
            bool  lo = (e <= eth);
            bool  ce = (u <= uth);
            float fe = lo ? (2.0f * re) : (1.0f - 2.0f * re);
            float fu = ce ? (2.0f * ru) : (1.0f - 2.0f * ru);
            float p  = fe * fu;
            den += p;
            num += (lo == ce) ? p : 0.0f;
        }
    }

    // Scalar tail (n may not be a multiple of 4).
    for (int i = (n4 << 2) + tid; i < n; i += stride) {
        float e  = err[i];
        float u  = unc[i];
        float re = half_logistic(e);
        float ru = half_logistic(u);
        bool  lo = (e <= eth);
        bool  ce = (u <= uth);
        float fe = lo ? (2.0f * re) : (1.0f - 2.0f * re);
        float fu = ce ? (2.0f * ru) : (1.0f - 2.0f * ru);
        float p  = fe * fu;
        den += p;
        num += (lo == ce) ? p : 0.0f;
    }

    // Warp reduction.
    #pragma unroll
    for (int off = 16; off > 0; off >>= 1) {
        num += __shfl_xor_sync(0xffffffffu, num, off);
        den += __shfl_xor_sync(0xffffffffu, den, off);
    }

    // Block reduction.
    __shared__ float s_num[8];
    __shared__ float s_den[8];
    __shared__ int   s_last;
    const int lane = threadIdx.x & 31;
    const int wid  = threadIdx.x >> 5;
    if (lane == 0) {
        s_num[wid] = num;
        s_den[wid] = den;
    }
    __syncthreads();
    if (wid == 0) {
        const int nw = blockDim.x >> 5;
        num = (lane < nw) ? s_num[lane] : 0.0f;
        den = (lane < nw) ? s_den[lane] : 0.0f;
        #pragma unroll
        for (int off = 4; off > 0; off >>= 1) {
            num += __shfl_xor_sync(0xffffffffu, num, off);
            den += __shfl_xor_sync(0xffffffffu, den, off);
        }
        if (lane == 0) {
            atomicAdd(&g_num, (double)num);
            atomicAdd(&g_den, (double)den);
            __threadfence();
            unsigned ticket = atomicAdd(&g_count, 1u);
            s_last = (ticket == gridDim.x - 1) ? 1 : 0;
        }
    }
    __syncthreads();

    // Last block finalizes and resets state for the next replay.
    if (threadIdx.x == 0 && s_last) {
        double eau  = g_num / (g_den + 1e-10);
        double loss = -log(eau + 1e-10);
        out[0] = (float)loss;
        g_num   = 0.0;
        g_den   = 0.0;
        g_count = 0u;
    }
}

extern "C" void kernel_launch(void* const* d_in, const int* in_sizes, int n_in,
                              void* d_out, int out_size)
{
    const float* err   = (const float*)d_in[0];
    const float* unc   = (const float*)d_in[1];
    const float* eth_p = (const float*)d_in[2];
    const float* uth_p = (const float*)d_in[3];
    float* out = (float*)d_out;
    const int n = in_sizes[0];

    eau_fused_kernel<<<2048, 256>>>(err, unc, eth_p, uth_p, out, n);
}